// round 5
// baseline (speedup 1.0000x reference)
#include <cuda_runtime.h>

#define WARPS 6
#define MAXN 20
#define CH 5

__device__ __forceinline__ void fma4(float& acc, const float4 a, const float4 b) {
    acc = fmaf(a.x, b.x, acc);
    acc = fmaf(a.y, b.y, acc);
    acc = fmaf(a.z, b.z, acc);
    acc = fmaf(a.w, b.w, acc);
}

__device__ __forceinline__ float wsum(float v) {
#pragma unroll
    for (int o = 16; o > 0; o >>= 1) v += __shfl_xor_sync(0xffffffffu, v, o);
    return v;
}

__global__ void __launch_bounds__(WARPS * 32)
mp_kernel(const float* __restrict__ node_feats, const int* __restrict__ n_nodes,
          const float* __restrict__ rnn_state, const float* __restrict__ prev_op,
          const float* __restrict__ ne_w, const float* __restrict__ ne_b,
          const float* __restrict__ mp1_w1, const float* __restrict__ mp1_b1,
          const float* __restrict__ mp1_w2, const float* __restrict__ mp1_b2,
          const float* __restrict__ n1_g, const float* __restrict__ n1_b,
          const float* __restrict__ mp2_w1, const float* __restrict__ mp2_b1,
          const float* __restrict__ mp2_w2, const float* __restrict__ mp2_b2,
          const float* __restrict__ n2_g, const float* __restrict__ n2_b,
          const float* __restrict__ gru_wih, const float* __restrict__ gru_whh,
          const float* __restrict__ gru_bih, const float* __restrict__ gru_bhh,
          const float* __restrict__ op_w, const float* __restrict__ op_b,
          const float* __restrict__ c1_w, const float* __restrict__ c1_b,
          const float* __restrict__ c2_w, const float* __restrict__ c2_b,
          const float* __restrict__ pq_w, const float* __restrict__ pq_b,
          const float* __restrict__ pk_w, const float* __restrict__ pk_b,
          float* __restrict__ out, int B)
{
    __shared__ float s_h[WARPS][MAXN * 64];   // per-element node features h
    __shared__ float s_u[WARPS][CH * 64];     // relu intermediate (aliased: nf at start)
    __shared__ float s_m[WARPS][64];          // msg / graph_vec
    __shared__ float s_a[WARPS][64];          // rnn_state, later query
    __shared__ float s_b[WARPS][64];          // new_state

    const int warp = threadIdx.x >> 5;
    const int lane = threadIdx.x & 31;
    const long b = (long)blockIdx.x * WARPS + warp;
    if (b >= B) return;

    const int o0 = lane, o1 = lane + 32;
    const int cnt = n_nodes[b];
    const float inv = 1.0f / (float)cnt;

    float* sh = s_h[warp];
    float* su = s_u[warp];
    float* sm = s_m[warp];
    float* sa = s_a[warp];
    float* sb = s_b[warp];

    const long OC1 = (long)B * 8;
    const long OC2 = (long)B * 18;
    const long OPTR = (long)B * 28;
    const long OST = (long)B * 48;

    // ---- load node feats (only cnt rows needed) into su (alias) ----
    {
        const float* nf = node_feats + b * (MAXN * 16);
        const int tot = cnt * 16;
        for (int i = lane; i < tot; i += 32) su[i] = nf[i];
    }
    // rnn_state and prev_op
    const float st0 = rnn_state[b * 64 + o0];
    const float st1 = rnn_state[b * 64 + o1];
    sa[o0] = st0; sa[o1] = st1;
    const float4 pva = *(const float4*)(prev_op + b * 8);
    const float4 pvb = *(const float4*)(prev_op + b * 8 + 4);
    __syncwarp();

    // ---- encoder: h = nf @ ne_w^T + ne_b ; msg = masked mean ----
    float msg0 = 0.f, msg1 = 0.f;
    {
        float4 w0[4], w1[4];
#pragma unroll
        for (int kc = 0; kc < 4; kc++) {
            w0[kc] = *(const float4*)(ne_w + o0 * 16 + kc * 4);
            w1[kc] = *(const float4*)(ne_w + o1 * 16 + kc * 4);
        }
        const float nb0 = ne_b[o0], nb1 = ne_b[o1];
#pragma unroll
        for (int c = 0; c < 4; c++) {
            const int base = c * CH;
            if (base < cnt) {
                float a0[CH], a1[CH];
#pragma unroll
                for (int i = 0; i < CH; i++) { a0[i] = nb0; a1[i] = nb1; }
#pragma unroll
                for (int kc = 0; kc < 4; kc++) {
#pragma unroll
                    for (int i = 0; i < CH; i++) {
                        float4 xv = *(const float4*)(su + (base + i) * 16 + kc * 4);
                        fma4(a0[i], xv, w0[kc]);
                        fma4(a1[i], xv, w1[kc]);
                    }
                }
#pragma unroll
                for (int i = 0; i < CH; i++) {
                    const int n = base + i;
                    if (n < cnt) {
                        msg0 += a0[i]; msg1 += a1[i];
                        sh[n * 64 + o0] = a0[i];
                        sh[n * 64 + o1] = a1[i];
                    }
                }
            }
        }
    }
    msg0 *= inv; msg1 *= inv;
    __syncwarp();
    sm[o0] = msg0; sm[o1] = msg1;
    __syncwarp();

    // ---- two message-passing blocks ----
#pragma unroll 1
    for (int blk = 0; blk < 2; blk++) {
        const float* w1p = blk ? mp2_w1 : mp1_w1;
        const float* b1p = blk ? mp2_b1 : mp1_b1;
        const float* w2p = blk ? mp2_w2 : mp1_w2;
        const float* b2p = blk ? mp2_b2 : mp1_b2;
        const float* gp  = blk ? n2_g : n1_g;
        const float* lbp = blk ? n2_b : n1_b;

        // msg-dependent part of layer1 (row-invariant)
        float mm0 = b1p[o0], mm1 = b1p[o1];
        const float* w1r0 = w1p + o0 * 128;
        const float* w1r1 = w1p + o1 * 128;
#pragma unroll
        for (int kc = 0; kc < 16; kc++) {
            float4 xv = *(const float4*)(sm + kc * 4);
            fma4(mm0, xv, *(const float4*)(w1r0 + 64 + kc * 4));
            fma4(mm1, xv, *(const float4*)(w1r1 + 64 + kc * 4));
        }
        const float bb20 = b2p[o0], bb21 = b2p[o1];
        const float g0 = gp[o0], g1 = gp[o1];
        const float lb0 = lbp[o0], lb1 = lbp[o1];
        const float* w2r0 = w2p + o0 * 64;
        const float* w2r1 = w2p + o1 * 64;

        float nm0 = 0.f, nm1 = 0.f;
#pragma unroll
        for (int c = 0; c < 4; c++) {
            const int base = c * CH;
            if (base < cnt) {
                // layer1: u = relu(h @ W1a^T + mm)
                float a0[CH], a1[CH];
#pragma unroll
                for (int i = 0; i < CH; i++) { a0[i] = mm0; a1[i] = mm1; }
#pragma unroll
                for (int kc = 0; kc < 16; kc++) {
                    float4 wa = *(const float4*)(w1r0 + kc * 4);
                    float4 wb = *(const float4*)(w1r1 + kc * 4);
#pragma unroll
                    for (int i = 0; i < CH; i++) {
                        float4 xv = *(const float4*)(sh + (base + i) * 64 + kc * 4);
                        fma4(a0[i], xv, wa);
                        fma4(a1[i], xv, wb);
                    }
                }
#pragma unroll
                for (int i = 0; i < CH; i++) {
                    su[i * 64 + o0] = fmaxf(a0[i], 0.f);
                    su[i * 64 + o1] = fmaxf(a1[i], 0.f);
                }
                __syncwarp();
                // layer2 + residual + LN + mask
                float v0[CH], v1[CH];
#pragma unroll
                for (int i = 0; i < CH; i++) { v0[i] = bb20; v1[i] = bb21; }
#pragma unroll
                for (int kc = 0; kc < 16; kc++) {
                    float4 wa = *(const float4*)(w2r0 + kc * 4);
                    float4 wb = *(const float4*)(w2r1 + kc * 4);
#pragma unroll
                    for (int i = 0; i < CH; i++) {
                        float4 xv = *(const float4*)(su + i * 64 + kc * 4);
                        fma4(v0[i], xv, wa);
                        fma4(v1[i], xv, wb);
                    }
                }
#pragma unroll
                for (int i = 0; i < CH; i++) {
                    const int n = base + i;
                    if (n < cnt) {
                        float x0 = v0[i] + sh[n * 64 + o0];
                        float x1v = v1[i] + sh[n * 64 + o1];
                        float mu = wsum(x0 + x1v) * (1.0f / 64.0f);
                        float d0 = x0 - mu, d1 = x1v - mu;
                        float var = wsum(d0 * d0 + d1 * d1) * (1.0f / 64.0f);
                        float rs = rsqrtf(var + 1e-5f);
                        float h0 = d0 * rs * g0 + lb0;
                        float h1 = d1 * rs * g1 + lb1;
                        nm0 += h0; nm1 += h1;
                        sh[n * 64 + o0] = h0;
                        sh[n * 64 + o1] = h1;
                    }
                }
                __syncwarp();
            }
        }
        msg0 = nm0 * inv; msg1 = nm1 * inv;
        __syncwarp();
        sm[o0] = msg0; sm[o1] = msg1;
        __syncwarp();
    }

    // ---- GRU cell: x = [graph_vec, prev_op] ----
    const float* wr0 = gru_wih + (long)o0 * 72;
    const float* wr1 = gru_wih + (long)o1 * 72;
    const float* wz0 = gru_wih + (long)(64 + o0) * 72;
    const float* wz1 = gru_wih + (long)(64 + o1) * 72;
    const float* wn0 = gru_wih + (long)(128 + o0) * 72;
    const float* wn1 = gru_wih + (long)(128 + o1) * 72;
    const float* hr0 = gru_whh + (long)o0 * 64;
    const float* hr1 = gru_whh + (long)o1 * 64;
    const float* hz0 = gru_whh + (long)(64 + o0) * 64;
    const float* hz1 = gru_whh + (long)(64 + o1) * 64;
    const float* hn0 = gru_whh + (long)(128 + o0) * 64;
    const float* hn1 = gru_whh + (long)(128 + o1) * 64;

    float gir0 = gru_bih[o0],       gir1 = gru_bih[o1];
    float giz0 = gru_bih[64 + o0],  giz1 = gru_bih[64 + o1];
    float gin0 = gru_bih[128 + o0], gin1 = gru_bih[128 + o1];
    float ghr0 = gru_bhh[o0],       ghr1 = gru_bhh[o1];
    float ghz0 = gru_bhh[64 + o0],  ghz1 = gru_bhh[64 + o1];
    float ghn0 = gru_bhh[128 + o0], ghn1 = gru_bhh[128 + o1];
#pragma unroll
    for (int kc = 0; kc < 16; kc++) {
        float4 xv = *(const float4*)(sm + kc * 4);
        fma4(gir0, xv, *(const float4*)(wr0 + kc * 4));
        fma4(gir1, xv, *(const float4*)(wr1 + kc * 4));
        fma4(giz0, xv, *(const float4*)(wz0 + kc * 4));
        fma4(giz1, xv, *(const float4*)(wz1 + kc * 4));
        fma4(gin0, xv, *(const float4*)(wn0 + kc * 4));
        fma4(gin1, xv, *(const float4*)(wn1 + kc * 4));
        float4 xs = *(const float4*)(sa + kc * 4);
        fma4(ghr0, xs, *(const float4*)(hr0 + kc * 4));
        fma4(ghr1, xs, *(const float4*)(hr1 + kc * 4));
        fma4(ghz0, xs, *(const float4*)(hz0 + kc * 4));
        fma4(ghz1, xs, *(const float4*)(hz1 + kc * 4));
        fma4(ghn0, xs, *(const float4*)(hn0 + kc * 4));
        fma4(ghn1, xs, *(const float4*)(hn1 + kc * 4));
    }
    // prev_op part (columns 64..71 of wih)
    fma4(gir0, pva, *(const float4*)(wr0 + 64));
    fma4(gir0, pvb, *(const float4*)(wr0 + 68));
    fma4(gir1, pva, *(const float4*)(wr1 + 64));
    fma4(gir1, pvb, *(const float4*)(wr1 + 68));
    fma4(giz0, pva, *(const float4*)(wz0 + 64));
    fma4(giz0, pvb, *(const float4*)(wz0 + 68));
    fma4(giz1, pva, *(const float4*)(wz1 + 64));
    fma4(giz1, pvb, *(const float4*)(wz1 + 68));
    fma4(gin0, pva, *(const float4*)(wn0 + 64));
    fma4(gin0, pvb, *(const float4*)(wn0 + 68));
    fma4(gin1, pva, *(const float4*)(wn1 + 64));
    fma4(gin1, pvb, *(const float4*)(wn1 + 68));

    const float r0 = 1.0f / (1.0f + expf(-(gir0 + ghr0)));
    const float r1 = 1.0f / (1.0f + expf(-(gir1 + ghr1)));
    const float z0 = 1.0f / (1.0f + expf(-(giz0 + ghz0)));
    const float z1 = 1.0f / (1.0f + expf(-(giz1 + ghz1)));
    const float nn0 = tanhf(gin0 + r0 * ghn0);
    const float nn1 = tanhf(gin1 + r1 * ghn1);
    const float ns0 = (1.0f - z0) * nn0 + z0 * st0;
    const float ns1 = (1.0f - z1) * nn1 + z1 * st1;

    out[OST + b * 64 + o0] = ns0;
    out[OST + b * 64 + o1] = ns1;
    sb[o0] = ns0; sb[o1] = ns1;
    __syncwarp();

    // ---- heads: lanes 0-7 op, 8-17 c1, 18-27 c2 in parallel ----
    {
        const float* hw = nullptr; float hb = 0.f; long off = 0;
        if (lane < 8)       { hw = op_w + lane * 64;        hb = op_b[lane];      off = b * 8 + lane; }
        else if (lane < 18) { int t = lane - 8;  hw = c1_w + t * 64; hb = c1_b[t]; off = OC1 + b * 10 + t; }
        else if (lane < 28) { int t = lane - 18; hw = c2_w + t * 64; hb = c2_b[t]; off = OC2 + b * 10 + t; }
        if (hw) {
            float acc = hb;
#pragma unroll
            for (int kc = 0; kc < 16; kc++) {
                float4 xv = *(const float4*)(sb + kc * 4);
                float4 wv = *(const float4*)(hw + kc * 4);
                fma4(acc, xv, wv);
            }
            out[off] = acc;
        }
    }

    // ---- query, then qa = pk_w^T @ q (avoids materializing keys) ----
    float q0 = pq_b[o0], q1 = pq_b[o1];
#pragma unroll
    for (int kc = 0; kc < 16; kc++) {
        float4 xv = *(const float4*)(sb + kc * 4);
        fma4(q0, xv, *(const float4*)(pq_w + o0 * 64 + kc * 4));
        fma4(q1, xv, *(const float4*)(pq_w + o1 * 64 + kc * 4));
    }
    __syncwarp();
    sa[o0] = q0; sa[o1] = q1;
    __syncwarp();

    float qa0 = 0.f, qa1 = 0.f;
#pragma unroll 8
    for (int o = 0; o < 64; o++) {
        const float qv = sa[o];
        qa0 = fmaf(qv, pk_w[o * 64 + o0], qa0);
        qa1 = fmaf(qv, pk_w[o * 64 + o1], qa1);
    }
    const float qb = wsum(q0 * pk_b[o0] + q1 * pk_b[o1]);

    // ---- pointer logits ----
    for (int n = 0; n < MAXN; n++) {
        float val = -1e9f;
        if (n < cnt) {
            float p = sh[n * 64 + o0] * qa0 + sh[n * 64 + o1] * qa1;
            val = wsum(p) + qb;
        }
        if (lane == 0) out[OPTR + b * 20 + n] = val;
    }
}

extern "C" void kernel_launch(void* const* d_in, const int* in_sizes, int n_in,
                              void* d_out, int out_size) {
    const int B = in_sizes[1];  // n_nodes element count
    const int blocks = (B + WARPS - 1) / WARPS;
    mp_kernel<<<blocks, WARPS * 32>>>(
        (const float*)d_in[0], (const int*)d_in[1],
        (const float*)d_in[2], (const float*)d_in[3],
        (const float*)d_in[4], (const float*)d_in[5],
        (const float*)d_in[6], (const float*)d_in[7],
        (const float*)d_in[8], (const float*)d_in[9],
        (const float*)d_in[10], (const float*)d_in[11],
        (const float*)d_in[12], (const float*)d_in[13],
        (const float*)d_in[14], (const float*)d_in[15],
        (const float*)d_in[16], (const float*)d_in[17],
        (const float*)d_in[18], (const float*)d_in[19],
        (const float*)d_in[20], (const float*)d_in[21],
        (const float*)d_in[22], (const float*)d_in[23],
        (const float*)d_in[24], (const float*)d_in[25],
        (const float*)d_in[26], (const float*)d_in[27],
        (const float*)d_in[28], (const float*)d_in[29],
        (const float*)d_in[30], (const float*)d_in[31],
        (float*)d_out, B);
}

// round 6
// speedup vs baseline: 2.5654x; 2.5654x over previous
#include <cuda_runtime.h>

#define WARPS 16
#define THREADS (WARPS * 32)
#define MAXN 20
#define CH 5

// ---- prep scratch layout (floats) ----
// staged block (copied to smem by each block):
//   [0,8448)      mp1_w1 padded [64][132]
//   [8448,16896)  mp2_w1 padded [64][132]
//   [16896,21248) mp1_w2 padded [64][68]
//   [21248,25600) mp2_w2 padded [64][68]
//   [25600,26880) ne_w   padded [64][20]
#define STAGED_FLOATS 26880
__device__ __align__(16) float g_staged[STAGED_FLOATS];
__device__ float2 g_wihT2[72 * 96];   // [k][gate][lane] -> {W[g*64+l][k], W[g*64+l+32][k]}
__device__ float2 g_whhT2[64 * 96];
__device__ float2 g_pqT2[64 * 32];
__device__ float  g_headsT[64 * 32];  // [k][t], t: 0-7 op, 8-17 c1, 18-27 c2, 28-31 zero

__global__ void prep_kernel(const float* __restrict__ mp1_w1, const float* __restrict__ mp1_w2,
                            const float* __restrict__ mp2_w1, const float* __restrict__ mp2_w2,
                            const float* __restrict__ ne_w,
                            const float* __restrict__ gru_wih, const float* __restrict__ gru_whh,
                            const float* __restrict__ pq_w,
                            const float* __restrict__ op_w, const float* __restrict__ c1_w,
                            const float* __restrict__ c2_w)
{
    const int tid = blockIdx.x * blockDim.x + threadIdx.x;
    const int stride = gridDim.x * blockDim.x;
    for (int i = tid; i < 64 * 132; i += stride) {
        int r = i / 132, c = i % 132;
        g_staged[i]        = (c < 128) ? mp1_w1[r * 128 + c] : 0.f;
        g_staged[8448 + i] = (c < 128) ? mp2_w1[r * 128 + c] : 0.f;
    }
    for (int i = tid; i < 64 * 68; i += stride) {
        int r = i / 68, c = i % 68;
        g_staged[16896 + i] = (c < 64) ? mp1_w2[r * 64 + c] : 0.f;
        g_staged[21248 + i] = (c < 64) ? mp2_w2[r * 64 + c] : 0.f;
    }
    for (int i = tid; i < 64 * 20; i += stride) {
        int r = i / 20, c = i % 20;
        g_staged[25600 + i] = (c < 16) ? ne_w[r * 16 + c] : 0.f;
    }
    for (int i = tid; i < 72 * 96; i += stride) {
        int k = i / 96, g = (i % 96) / 32, l = i % 32;
        g_wihT2[i] = make_float2(gru_wih[(g * 64 + l) * 72 + k],
                                 gru_wih[(g * 64 + l + 32) * 72 + k]);
    }
    for (int i = tid; i < 64 * 96; i += stride) {
        int k = i / 96, g = (i % 96) / 32, l = i % 32;
        g_whhT2[i] = make_float2(gru_whh[(g * 64 + l) * 64 + k],
                                 gru_whh[(g * 64 + l + 32) * 64 + k]);
    }
    for (int i = tid; i < 64 * 32; i += stride) {
        int k = i / 32, l = i % 32;
        g_pqT2[i] = make_float2(pq_w[l * 64 + k], pq_w[(l + 32) * 64 + k]);
        float hv = 0.f;
        if (l < 8)       hv = op_w[l * 64 + k];
        else if (l < 18) hv = c1_w[(l - 8) * 64 + k];
        else if (l < 28) hv = c2_w[(l - 18) * 64 + k];
        g_headsT[i] = hv;
    }
}

__device__ __forceinline__ void fma4(float& acc, const float4 a, const float4 b) {
    acc = fmaf(a.x, b.x, acc);
    acc = fmaf(a.y, b.y, acc);
    acc = fmaf(a.z, b.z, acc);
    acc = fmaf(a.w, b.w, acc);
}

__device__ __forceinline__ float wsum(float v) {
#pragma unroll
    for (int o = 16; o > 0; o >>= 1) v += __shfl_xor_sync(0xffffffffu, v, o);
    return v;
}

// per-warp activation floats: sh(1280) su(320) sm(64) sa(64) sb(64) = 1792
#define ACT_FLOATS 1792
#define SMEM_FLOATS (STAGED_FLOATS + WARPS * ACT_FLOATS)

__global__ void __launch_bounds__(THREADS)
mp_kernel(const float* __restrict__ node_feats, const int* __restrict__ n_nodes,
          const float* __restrict__ rnn_state, const float* __restrict__ prev_op,
          const float* __restrict__ ne_b,
          const float* __restrict__ mp1_b1, const float* __restrict__ mp1_b2,
          const float* __restrict__ n1_g, const float* __restrict__ n1_b,
          const float* __restrict__ mp2_b1, const float* __restrict__ mp2_b2,
          const float* __restrict__ n2_g, const float* __restrict__ n2_b,
          const float* __restrict__ gru_bih, const float* __restrict__ gru_bhh,
          const float* __restrict__ op_b, const float* __restrict__ c1_b,
          const float* __restrict__ c2_b,
          const float* __restrict__ pq_b,
          const float* __restrict__ pk_w, const float* __restrict__ pk_b,
          float* __restrict__ out, int B)
{
    extern __shared__ float smem[];

    // ---- stage weights (all threads) ----
    {
        const float4* src = (const float4*)g_staged;
        float4* dst = (float4*)smem;
        for (int i = threadIdx.x; i < STAGED_FLOATS / 4; i += THREADS) dst[i] = src[i];
    }
    __syncthreads();

    const int warp = threadIdx.x >> 5;
    const int lane = threadIdx.x & 31;
    const long b = (long)blockIdx.x * WARPS + warp;
    if (b >= B) return;

    const int o0 = lane, o1 = lane + 32;
    const int cnt = n_nodes[b];
    const float inv = 1.0f / (float)cnt;

    float* W1s0 = smem;
    float* W1s1 = smem + 8448;
    float* W2s0 = smem + 16896;
    float* W2s1 = smem + 21248;
    float* NEs  = smem + 25600;
    float* sh = smem + STAGED_FLOATS + warp * ACT_FLOATS;
    float* su = sh + 1280;
    float* sm = su + 320;
    float* sa = sm + 64;
    float* sb = sa + 64;

    const long OC1 = (long)B * 8;
    const long OC2 = (long)B * 18;
    const long OPTR = (long)B * 28;
    const long OST = (long)B * 48;

    // ---- load node feats (only cnt rows needed) into su (alias) ----
    {
        const float* nf = node_feats + b * (MAXN * 16);
        const int tot = cnt * 16;
        for (int i = lane; i < tot; i += 32) su[i] = nf[i];
    }
    const float st0 = rnn_state[b * 64 + o0];
    const float st1 = rnn_state[b * 64 + o1];
    sa[o0] = st0; sa[o1] = st1;
    const float4 pva = *(const float4*)(prev_op + b * 8);
    const float4 pvb = *(const float4*)(prev_op + b * 8 + 4);
    __syncwarp();

    // ---- encoder: h = nf @ ne_w^T + ne_b ; msg = masked mean ----
    float msg0 = 0.f, msg1 = 0.f;
    {
        float4 w0[4], w1[4];
#pragma unroll
        for (int kc = 0; kc < 4; kc++) {
            w0[kc] = *(const float4*)(NEs + o0 * 20 + kc * 4);
            w1[kc] = *(const float4*)(NEs + o1 * 20 + kc * 4);
        }
        const float nb0 = ne_b[o0], nb1 = ne_b[o1];
#pragma unroll
        for (int c = 0; c < 4; c++) {
            const int base = c * CH;
            if (base < cnt) {
                float a0[CH], a1[CH];
#pragma unroll
                for (int i = 0; i < CH; i++) { a0[i] = nb0; a1[i] = nb1; }
#pragma unroll
                for (int kc = 0; kc < 4; kc++) {
#pragma unroll
                    for (int i = 0; i < CH; i++) {
                        float4 xv = *(const float4*)(su + (base + i) * 16 + kc * 4);
                        fma4(a0[i], xv, w0[kc]);
                        fma4(a1[i], xv, w1[kc]);
                    }
                }
#pragma unroll
                for (int i = 0; i < CH; i++) {
                    const int n = base + i;
                    if (n < cnt) {
                        msg0 += a0[i]; msg1 += a1[i];
                        sh[n * 64 + o0] = a0[i];
                        sh[n * 64 + o1] = a1[i];
                    }
                }
            }
        }
    }
    msg0 *= inv; msg1 *= inv;
    __syncwarp();
    sm[o0] = msg0; sm[o1] = msg1;
    __syncwarp();

    // ---- two message-passing blocks (weights in smem, padded strides) ----
#pragma unroll 1
    for (int blk = 0; blk < 2; blk++) {
        const float* w1r0 = (blk ? W1s1 : W1s0) + o0 * 132;
        const float* w1r1 = (blk ? W1s1 : W1s0) + o1 * 132;
        const float* w2r0 = (blk ? W2s1 : W2s0) + o0 * 68;
        const float* w2r1 = (blk ? W2s1 : W2s0) + o1 * 68;
        const float* b1p = blk ? mp2_b1 : mp1_b1;
        const float* b2p = blk ? mp2_b2 : mp1_b2;
        const float* gp  = blk ? n2_g : n1_g;
        const float* lbp = blk ? n2_b : n1_b;

        // msg-dependent part of layer1 (row-invariant)
        float mm0 = b1p[o0], mm1 = b1p[o1];
#pragma unroll
        for (int kc = 0; kc < 16; kc++) {
            float4 xv = *(const float4*)(sm + kc * 4);
            fma4(mm0, xv, *(const float4*)(w1r0 + 64 + kc * 4));
            fma4(mm1, xv, *(const float4*)(w1r1 + 64 + kc * 4));
        }
        const float bb20 = b2p[o0], bb21 = b2p[o1];
        const float g0 = gp[o0], g1 = gp[o1];
        const float lb0 = lbp[o0], lb1 = lbp[o1];

        float nm0 = 0.f, nm1 = 0.f;
#pragma unroll
        for (int c = 0; c < 4; c++) {
            const int base = c * CH;
            if (base < cnt) {
                // layer1: u = relu(h @ W1a^T + mm)
                float a0[CH], a1[CH];
#pragma unroll
                for (int i = 0; i < CH; i++) { a0[i] = mm0; a1[i] = mm1; }
#pragma unroll
                for (int kc = 0; kc < 16; kc++) {
                    float4 wa = *(const float4*)(w1r0 + kc * 4);
                    float4 wb = *(const float4*)(w1r1 + kc * 4);
#pragma unroll
                    for (int i = 0; i < CH; i++) {
                        float4 xv = *(const float4*)(sh + (base + i) * 64 + kc * 4);
                        fma4(a0[i], xv, wa);
                        fma4(a1[i], xv, wb);
                    }
                }
#pragma unroll
                for (int i = 0; i < CH; i++) {
                    su[i * 64 + o0] = fmaxf(a0[i], 0.f);
                    su[i * 64 + o1] = fmaxf(a1[i], 0.f);
                }
                __syncwarp();
                // layer2 + residual + LN + mask
                float v0[CH], v1[CH];
#pragma unroll
                for (int i = 0; i < CH; i++) { v0[i] = bb20; v1[i] = bb21; }
#pragma unroll
                for (int kc = 0; kc < 16; kc++) {
                    float4 wa = *(const float4*)(w2r0 + kc * 4);
                    float4 wb = *(const float4*)(w2r1 + kc * 4);
#pragma unroll
                    for (int i = 0; i < CH; i++) {
                        float4 xv = *(const float4*)(su + i * 64 + kc * 4);
                        fma4(v0[i], xv, wa);
                        fma4(v1[i], xv, wb);
                    }
                }
#pragma unroll
                for (int i = 0; i < CH; i++) {
                    const int n = base + i;
                    if (n < cnt) {
                        float x0 = v0[i] + sh[n * 64 + o0];
                        float x1v = v1[i] + sh[n * 64 + o1];
                        float mu = wsum(x0 + x1v) * (1.0f / 64.0f);
                        float d0 = x0 - mu, d1 = x1v - mu;
                        float var = wsum(d0 * d0 + d1 * d1) * (1.0f / 64.0f);
                        float rs = rsqrtf(var + 1e-5f);
                        float h0 = d0 * rs * g0 + lb0;
                        float h1 = d1 * rs * g1 + lb1;
                        nm0 += h0; nm1 += h1;
                        sh[n * 64 + o0] = h0;
                        sh[n * 64 + o1] = h1;
                    }
                }
                __syncwarp();
            }
        }
        msg0 = nm0 * inv; msg1 = nm1 * inv;
        __syncwarp();
        sm[o0] = msg0; sm[o1] = msg1;
        __syncwarp();
    }

    // ---- GRU cell via transposed, lane-pair-packed weights (coalesced) ----
    float gir0 = gru_bih[o0],       gir1 = gru_bih[o1];
    float giz0 = gru_bih[64 + o0],  giz1 = gru_bih[64 + o1];
    float gin0 = gru_bih[128 + o0], gin1 = gru_bih[128 + o1];
    float ghr0 = gru_bhh[o0],       ghr1 = gru_bhh[o1];
    float ghz0 = gru_bhh[64 + o0],  ghz1 = gru_bhh[64 + o1];
    float ghn0 = gru_bhh[128 + o0], ghn1 = gru_bhh[128 + o1];
#pragma unroll 4
    for (int k = 0; k < 64; k++) {
        const float xm = sm[k];
        const float2* wk = g_wihT2 + k * 96;
        const float2 wr = wk[lane];
        const float2 wz = wk[32 + lane];
        const float2 wn = wk[64 + lane];
        gir0 = fmaf(xm, wr.x, gir0); gir1 = fmaf(xm, wr.y, gir1);
        giz0 = fmaf(xm, wz.x, giz0); giz1 = fmaf(xm, wz.y, giz1);
        gin0 = fmaf(xm, wn.x, gin0); gin1 = fmaf(xm, wn.y, gin1);
        const float xs = sa[k];
        const float2* vk = g_whhT2 + k * 96;
        const float2 vr = vk[lane];
        const float2 vz = vk[32 + lane];
        const float2 vn = vk[64 + lane];
        ghr0 = fmaf(xs, vr.x, ghr0); ghr1 = fmaf(xs, vr.y, ghr1);
        ghz0 = fmaf(xs, vz.x, ghz0); ghz1 = fmaf(xs, vz.y, ghz1);
        ghn0 = fmaf(xs, vn.x, ghn0); ghn1 = fmaf(xs, vn.y, ghn1);
    }
    {
        const float pv[8] = {pva.x, pva.y, pva.z, pva.w, pvb.x, pvb.y, pvb.z, pvb.w};
#pragma unroll
        for (int k = 0; k < 8; k++) {
            const float xp = pv[k];
            const float2* wk = g_wihT2 + (64 + k) * 96;
            const float2 wr = wk[lane];
            const float2 wz = wk[32 + lane];
            const float2 wn = wk[64 + lane];
            gir0 = fmaf(xp, wr.x, gir0); gir1 = fmaf(xp, wr.y, gir1);
            giz0 = fmaf(xp, wz.x, giz0); giz1 = fmaf(xp, wz.y, giz1);
            gin0 = fmaf(xp, wn.x, gin0); gin1 = fmaf(xp, wn.y, gin1);
        }
    }

    const float r0 = 1.0f / (1.0f + expf(-(gir0 + ghr0)));
    const float r1 = 1.0f / (1.0f + expf(-(gir1 + ghr1)));
    const float z0 = 1.0f / (1.0f + expf(-(giz0 + ghz0)));
    const float z1 = 1.0f / (1.0f + expf(-(giz1 + ghz1)));
    const float nn0 = tanhf(gin0 + r0 * ghn0);
    const float nn1 = tanhf(gin1 + r1 * ghn1);
    const float ns0 = (1.0f - z0) * nn0 + z0 * st0;
    const float ns1 = (1.0f - z1) * nn1 + z1 * st1;

    out[OST + b * 64 + o0] = ns0;
    out[OST + b * 64 + o1] = ns1;
    sb[o0] = ns0; sb[o1] = ns1;
    __syncwarp();

    // ---- heads via transposed matrix (coalesced; one output per lane) ----
    {
        float hb = 0.f; long off = -1;
        if (lane < 8)       { hb = op_b[lane];      off = b * 8 + lane; }
        else if (lane < 18) { hb = c1_b[lane - 8];  off = OC1 + b * 10 + (lane - 8); }
        else if (lane < 28) { hb = c2_b[lane - 18]; off = OC2 + b * 10 + (lane - 18); }
        float acc = hb;
#pragma unroll 4
        for (int k = 0; k < 64; k++) acc = fmaf(sb[k], g_headsT[k * 32 + lane], acc);
        if (off >= 0) out[off] = acc;
    }

    // ---- query via transposed pq, then qa = pk_w^T @ q ----
    float q0 = pq_b[o0], q1 = pq_b[o1];
#pragma unroll 4
    for (int k = 0; k < 64; k++) {
        const float xv = sb[k];
        const float2 w = g_pqT2[k * 32 + lane];
        q0 = fmaf(xv, w.x, q0); q1 = fmaf(xv, w.y, q1);
    }
    __syncwarp();
    sa[o0] = q0; sa[o1] = q1;
    __syncwarp();

    float qa0 = 0.f, qa1 = 0.f;
#pragma unroll 8
    for (int o = 0; o < 64; o++) {
        const float qv = sa[o];
        qa0 = fmaf(qv, pk_w[o * 64 + o0], qa0);
        qa1 = fmaf(qv, pk_w[o * 64 + o1], qa1);
    }
    const float qb = wsum(q0 * pk_b[o0] + q1 * pk_b[o1]);

    // ---- pointer logits ----
    for (int n = 0; n < MAXN; n++) {
        float val = -1e9f;
        if (n < cnt) {
            float p = sh[n * 64 + o0] * qa0 + sh[n * 64 + o1] * qa1;
            val = wsum(p) + qb;
        }
        if (lane == 0) out[OPTR + b * 20 + n] = val;
    }
}

extern "C" void kernel_launch(void* const* d_in, const int* in_sizes, int n_in,
                              void* d_out, int out_size) {
    const int B = in_sizes[1];  // n_nodes element count

    prep_kernel<<<64, 256>>>(
        (const float*)d_in[6],  (const float*)d_in[8],   // mp1_w1, mp1_w2
        (const float*)d_in[12], (const float*)d_in[14],  // mp2_w1, mp2_w2
        (const float*)d_in[4],                           // ne_w
        (const float*)d_in[18], (const float*)d_in[19],  // gru_wih, gru_whh
        (const float*)d_in[28],                          // pq_w
        (const float*)d_in[22], (const float*)d_in[24], (const float*)d_in[26]); // op_w,c1_w,c2_w

    const size_t smem_bytes = (size_t)SMEM_FLOATS * sizeof(float);
    cudaFuncSetAttribute(mp_kernel, cudaFuncAttributeMaxDynamicSharedMemorySize, (int)smem_bytes);

    const int blocks = (B + WARPS - 1) / WARPS;
    mp_kernel<<<blocks, THREADS, smem_bytes>>>(
        (const float*)d_in[0], (const int*)d_in[1],
        (const float*)d_in[2], (const float*)d_in[3],
        (const float*)d_in[5],                            // ne_b
        (const float*)d_in[7], (const float*)d_in[9],     // mp1_b1, mp1_b2
        (const float*)d_in[10], (const float*)d_in[11],   // n1_g, n1_b
        (const float*)d_in[13], (const float*)d_in[15],   // mp2_b1, mp2_b2
        (const float*)d_in[16], (const float*)d_in[17],   // n2_g, n2_b
        (const float*)d_in[20], (const float*)d_in[21],   // gru_bih, gru_bhh
        (const float*)d_in[23], (const float*)d_in[25], (const float*)d_in[27], // op_b, c1_b, c2_b
        (const float*)d_in[29],                           // pq_b
        (const float*)d_in[30], (const float*)d_in[31],   // pk_w, pk_b
        (float*)d_out, B);
}